// round 5
// baseline (speedup 1.0000x reference)
#include <cuda_runtime.h>
#include <cuda_bf16.h>
#include <cstdint>
#include <math.h>
#include <string.h>

// Problem shape (fixed)
#define BB 4
#define SS 2048
#define DD 1024
#define HH 16
#define DH 64
#define MROWS (BB*SS)   // 8192

// ---------------------------------------------------------------------------
// Scratch (__device__ globals; allocation-free rule). All bf16 hi/lo pairs.
// q/k/v layout: [B*H][S][64]
// ---------------------------------------------------------------------------
__device__ __nv_bfloat16 g_qh[(size_t)BB*HH*SS*DH];
__device__ __nv_bfloat16 g_ql[(size_t)BB*HH*SS*DH];
__device__ __nv_bfloat16 g_kh[(size_t)BB*HH*SS*DH];
__device__ __nv_bfloat16 g_kl[(size_t)BB*HH*SS*DH];
__device__ __nv_bfloat16 g_vh[(size_t)BB*HH*SS*DH];
__device__ __nv_bfloat16 g_vl[(size_t)BB*HH*SS*DH];

__device__ __nv_bfloat16 g_x_hi[(size_t)MROWS*DD];
__device__ __nv_bfloat16 g_x_lo[(size_t)MROWS*DD];
__device__ __nv_bfloat16 g_at_hi[(size_t)MROWS*DD];
__device__ __nv_bfloat16 g_at_lo[(size_t)MROWS*DD];
// transposed+split weights: [4][N][K], Wt[n][k] = W[k][n]; 0..3 = q,k,v,o
__device__ __nv_bfloat16 g_wt_hi[(size_t)4*DD*DD];
__device__ __nv_bfloat16 g_wt_lo[(size_t)4*DD*DD];

// ---------------------------------------------------------------------------
// Helpers (base-sm_103-safe)
// ---------------------------------------------------------------------------
__device__ __forceinline__ uint32_t smem_u32(const void* p) {
    uint32_t a;
    asm("{ .reg .u64 t; cvta.to.shared.u64 t, %1; cvt.u32.u64 %0, t; }"
        : "=r"(a) : "l"(p));
    return a;
}
#define CP_ASYNC16(dst_u32, src_ptr) \
    asm volatile("cp.async.cg.shared.global [%0], [%1], 16;" \
                 :: "r"(dst_u32), "l"(src_ptr))
#define CP_COMMIT() asm volatile("cp.async.commit_group;")
#define CP_WAIT1()  asm volatile("cp.async.wait_group 1;")
#define CP_WAIT0()  asm volatile("cp.async.wait_group 0;")

#define LDSM_X4(r0, r1, r2, r3, addr) \
    asm volatile("ldmatrix.sync.aligned.m8n8.x4.shared.b16 {%0,%1,%2,%3}, [%4];" \
                 : "=r"(r0), "=r"(r1), "=r"(r2), "=r"(r3) : "r"(addr))
#define LDSM_X4_T(r0, r1, r2, r3, addr) \
    asm volatile("ldmatrix.sync.aligned.m8n8.x4.trans.shared.b16 {%0,%1,%2,%3}, [%4];" \
                 : "=r"(r0), "=r"(r1), "=r"(r2), "=r"(r3) : "r"(addr))

#define MMA16816(d, a0, a1, a2, a3, b0, b1) \
    asm volatile("mma.sync.aligned.m16n8k16.row.col.f32.bf16.bf16.f32 " \
                 "{%0,%1,%2,%3}, {%4,%5,%6,%7}, {%8,%9}, {%0,%1,%2,%3};" \
                 : "+f"((d)[0]), "+f"((d)[1]), "+f"((d)[2]), "+f"((d)[3]) \
                 : "r"(a0), "r"(a1), "r"(a2), "r"(a3), "r"(b0), "r"(b1))

__device__ __forceinline__ uint32_t pack_bf2(__nv_bfloat16 a, __nv_bfloat16 b) {
    __nv_bfloat162 h; h.x = a; h.y = b;
    uint32_t u; memcpy(&u, &h, 4);
    return u;
}

// q scale: (1/sqrt(64)) * log2(e), so softmax runs in exp2 domain
#define QSCALE 0.1803368801111204f

// ---------------------------------------------------------------------------
// Prep kernels
// ---------------------------------------------------------------------------
__global__ void __launch_bounds__(256)
split_kernel(const float* __restrict__ in, __nv_bfloat16* __restrict__ hi,
             __nv_bfloat16* __restrict__ lo) {
    size_t i = ((size_t)blockIdx.x * 256 + threadIdx.x) * 4;
    float4 v = *(const float4*)(in + i);
    __nv_bfloat16 h0 = __float2bfloat16(v.x);
    __nv_bfloat16 h1 = __float2bfloat16(v.y);
    __nv_bfloat16 h2 = __float2bfloat16(v.z);
    __nv_bfloat16 h3 = __float2bfloat16(v.w);
    *(uint32_t*)(hi + i)     = pack_bf2(h0, h1);
    *(uint32_t*)(hi + i + 2) = pack_bf2(h2, h3);
    *(uint32_t*)(lo + i)     = pack_bf2(__float2bfloat16(v.x - __bfloat162float(h0)),
                                        __float2bfloat16(v.y - __bfloat162float(h1)));
    *(uint32_t*)(lo + i + 2) = pack_bf2(__float2bfloat16(v.z - __bfloat162float(h2)),
                                        __float2bfloat16(v.w - __bfloat162float(h3)));
}

__global__ void __launch_bounds__(256)
transpose_split_w(const float* __restrict__ Wq, const float* __restrict__ Wk,
                  const float* __restrict__ Wv, const float* __restrict__ Wo) {
    __shared__ float t[32][33];
    const float* W = (blockIdx.z == 0) ? Wq : (blockIdx.z == 1) ? Wk :
                     (blockIdx.z == 2) ? Wv : Wo;
    __nv_bfloat16* Th = g_wt_hi + (size_t)blockIdx.z * DD * DD;
    __nv_bfloat16* Tl = g_wt_lo + (size_t)blockIdx.z * DD * DD;
    int k0 = blockIdx.y * 32, n0 = blockIdx.x * 32;
    int tx = threadIdx.x, ty = threadIdx.y;
    #pragma unroll
    for (int i = ty; i < 32; i += 8)
        t[i][tx] = W[(size_t)(k0 + i) * DD + n0 + tx];
    __syncthreads();
    #pragma unroll
    for (int i = ty; i < 32; i += 8) {
        float v = t[tx][i];
        size_t o = (size_t)(n0 + i) * DD + k0 + tx;
        __nv_bfloat16 h = __float2bfloat16(v);
        Th[o] = h;
        Tl[o] = __float2bfloat16(v - __bfloat162float(h));
    }
}

// ---------------------------------------------------------------------------
// Split-bf16 GEMM on mma.sync. MODE 0: fp32 out [M][N]. MODE 1: bf16 hi/lo
// split-scatter into [B*H][S][64] with optional scale.
// ng-pipelined B-fragment loads hide LDSM latency under MMAs.
// ---------------------------------------------------------------------------
#define KC 32
#define NCHUNK (DD / KC)              // 32
#define ROW_B 80
#define TILE_BY (128 * ROW_B)
#define STAGE_BY (4 * TILE_BY)
#define SMEM_MMA (2 * STAGE_BY)       // 81920

template<int MODE>
__device__ __forceinline__ void mma_gemm_body(const __nv_bfloat16* __restrict__ Ah,
                                              const __nv_bfloat16* __restrict__ Al,
                                              const __nv_bfloat16* __restrict__ Bh,
                                              const __nv_bfloat16* __restrict__ Bl,
                                              const float* __restrict__ bias,
                                              float* __restrict__ C,
                                              __nv_bfloat16* __restrict__ Hi,
                                              __nv_bfloat16* __restrict__ Lo,
                                              float scale)
{
    extern __shared__ char dynsmem[];
    const uint32_t base_u = smem_u32(dynsmem);

    const int tid  = threadIdx.x;
    const int wid  = tid >> 5, lane = tid & 31;
    const int wm   = wid & 3;
    const int wn   = wid >> 2;
    const int m0   = blockIdx.y * 128;
    const int n0   = blockIdx.x * 128;

    const __nv_bfloat16* srcs[4] = { Ah, Al, Bh, Bl };
    const int rowbase[4] = { m0, m0, n0, n0 };

    auto issue_stage = [&](int c, int st) {
        #pragma unroll
        for (int tile = 0; tile < 4; ++tile) {
            const __nv_bfloat16* src = srcs[tile] + (size_t)rowbase[tile] * DD + c * KC;
            uint32_t dst = base_u + st * STAGE_BY + tile * TILE_BY;
            #pragma unroll
            for (int it = 0; it < 2; ++it) {
                int idx = tid + it * 256;
                int row = idx >> 2;
                int seg = idx & 3;
                CP_ASYNC16(dst + row * ROW_B + seg * 16,
                           src + (size_t)row * DD + seg * 8);
            }
        }
    };

    float acc[2][8][4];
    #pragma unroll
    for (int i = 0; i < 2; ++i)
        #pragma unroll
        for (int j = 0; j < 8; ++j)
            #pragma unroll
            for (int q = 0; q < 4; ++q) acc[i][j][q] = 0.f;

    const int arow = wm * 32 + (lane & 15);
    const int akof = ((lane >> 4) & 1) * 16;
    const int brow = wn * 64 + (lane & 7) + ((lane >> 4) & 1) * 8;
    const int bkof = ((lane >> 3) & 1) * 16;

    issue_stage(0, 0); CP_COMMIT();
    issue_stage(1, 1); CP_COMMIT();

    for (int c = 0; c < NCHUNK; ++c) {
        const int st = c & 1;
        if (c + 2 < NCHUNK) CP_WAIT1(); else CP_WAIT0();
        __syncthreads();

        const uint32_t sA_hi = base_u + st * STAGE_BY;
        const uint32_t sA_lo = sA_hi + TILE_BY;
        const uint32_t sB_hi = sA_hi + 2 * TILE_BY;
        const uint32_t sB_lo = sA_hi + 3 * TILE_BY;

        #pragma unroll
        for (int ks = 0; ks < 2; ++ks) {
            uint32_t ah[2][4], al[2][4];
            #pragma unroll
            for (int mf = 0; mf < 2; ++mf) {
                uint32_t ra = (arow + mf * 16) * ROW_B + ks * 32 + akof;
                LDSM_X4(ah[mf][0], ah[mf][1], ah[mf][2], ah[mf][3], sA_hi + ra);
                LDSM_X4(al[mf][0], al[mf][1], al[mf][2], al[mf][3], sA_lo + ra);
            }
            // ng-pipelined B loads: buf holds 2 n-fragments (4 regs hi, 4 lo)
            uint32_t bh[2][4], bl[2][4];
            {
                uint32_t rb = (brow) * ROW_B + ks * 32 + bkof;
                LDSM_X4(bh[0][0], bh[0][1], bh[0][2], bh[0][3], sB_hi + rb);
                LDSM_X4(bl[0][0], bl[0][1], bl[0][2], bl[0][3], sB_lo + rb);
            }
            #pragma unroll
            for (int ng = 0; ng < 4; ++ng) {
                const int cur = ng & 1, nxt = cur ^ 1;
                if (ng < 3) {
                    uint32_t rb = (brow + (ng + 1) * 16) * ROW_B + ks * 32 + bkof;
                    LDSM_X4(bh[nxt][0], bh[nxt][1], bh[nxt][2], bh[nxt][3], sB_hi + rb);
                    LDSM_X4(bl[nxt][0], bl[nxt][1], bl[nxt][2], bl[nxt][3], sB_lo + rb);
                }
                #pragma unroll
                for (int mf = 0; mf < 2; ++mf) {
                    MMA16816(acc[mf][2*ng],   ah[mf][0], ah[mf][1], ah[mf][2], ah[mf][3],
                             bh[cur][0], bh[cur][1]);
                    MMA16816(acc[mf][2*ng],   ah[mf][0], ah[mf][1], ah[mf][2], ah[mf][3],
                             bl[cur][0], bl[cur][1]);
                    MMA16816(acc[mf][2*ng],   al[mf][0], al[mf][1], al[mf][2], al[mf][3],
                             bh[cur][0], bh[cur][1]);
                    MMA16816(acc[mf][2*ng+1], ah[mf][0], ah[mf][1], ah[mf][2], ah[mf][3],
                             bh[cur][2], bh[cur][3]);
                    MMA16816(acc[mf][2*ng+1], ah[mf][0], ah[mf][1], ah[mf][2], ah[mf][3],
                             bl[cur][2], bl[cur][3]);
                    MMA16816(acc[mf][2*ng+1], al[mf][0], al[mf][1], al[mf][2], al[mf][3],
                             bh[cur][2], bh[cur][3]);
                }
            }
        }
        __syncthreads();
        if (c + 2 < NCHUNK) { issue_stage(c + 2, st); CP_COMMIT(); }
    }

    const int mrow = lane >> 2;
    const int ncol = (lane & 3) * 2;
    #pragma unroll
    for (int mf = 0; mf < 2; ++mf) {
        #pragma unroll
        for (int nf = 0; nf < 8; ++nf) {
            int m = m0 + wm * 32 + mf * 16 + mrow;
            int n = n0 + wn * 64 + nf * 8 + ncol;
            float b0 = bias[n], b1 = bias[n + 1];
            float v00 = (acc[mf][nf][0] + b0) * scale;
            float v01 = (acc[mf][nf][1] + b1) * scale;
            float v10 = (acc[mf][nf][2] + b0) * scale;
            float v11 = (acc[mf][nf][3] + b1) * scale;
            if (MODE == 0) {
                *(float2*)&C[(size_t)m * DD + n]       = make_float2(v00, v01);
                *(float2*)&C[(size_t)(m + 8) * DD + n] = make_float2(v10, v11);
            } else {
                int b = m >> 11, h = n >> 6, d = n & 63;
                int s  = m & (SS - 1);
                size_t o0 = (((size_t)(b * HH + h)) * SS + s) * DH + d;
                size_t o1 = o0 + 8 * DH;
                __nv_bfloat16 h00 = __float2bfloat16(v00), h01 = __float2bfloat16(v01);
                __nv_bfloat16 h10 = __float2bfloat16(v10), h11 = __float2bfloat16(v11);
                *(uint32_t*)(Hi + o0) = pack_bf2(h00, h01);
                *(uint32_t*)(Hi + o1) = pack_bf2(h10, h11);
                *(uint32_t*)(Lo + o0) = pack_bf2(
                    __float2bfloat16(v00 - __bfloat162float(h00)),
                    __float2bfloat16(v01 - __bfloat162float(h01)));
                *(uint32_t*)(Lo + o1) = pack_bf2(
                    __float2bfloat16(v10 - __bfloat162float(h10)),
                    __float2bfloat16(v11 - __bfloat162float(h11)));
            }
        }
    }
}

__global__ void __launch_bounds__(256)
qkv_mma_kernel(const float* __restrict__ bq, const float* __restrict__ bk,
               const float* __restrict__ bv) {
    int z = blockIdx.z;
    __nv_bfloat16* Hi = (z == 0) ? g_qh : (z == 1) ? g_kh : g_vh;
    __nv_bfloat16* Lo = (z == 0) ? g_ql : (z == 1) ? g_kl : g_vl;
    const float* bias = (z == 0) ? bq : (z == 1) ? bk : bv;
    float scale = (z == 0) ? QSCALE : 1.0f;   // fold 1/sqrt(Dh)*log2e into q
    mma_gemm_body<1>(g_x_hi, g_x_lo,
                     g_wt_hi + (size_t)z * DD * DD, g_wt_lo + (size_t)z * DD * DD,
                     bias, nullptr, Hi, Lo, scale);
}

__global__ void __launch_bounds__(256)
outproj_mma_kernel(const float* __restrict__ bo, float* __restrict__ out) {
    mma_gemm_body<0>(g_at_hi, g_at_lo,
                     g_wt_hi + (size_t)3 * DD * DD, g_wt_lo + (size_t)3 * DD * DD,
                     bo, out, nullptr, nullptr, 1.0f);
}

// ---------------------------------------------------------------------------
// Tensor-core flash attention (split-bf16, causal, exp2 domain).
// CTA: 128 Q rows x 64 KV tile, 8 warps, 256 threads. Qh register-resident.
// ---------------------------------------------------------------------------
#define AROWB 144
#define ATILE_BY (64 * AROWB)
#define AQ_BY (128 * AROWB)
#define ASTAGE_BY (4 * ATILE_BY)
#define SMEM_ATT (2 * AQ_BY + 2 * ASTAGE_BY)   // 110592

__global__ void __launch_bounds__(256, 2)
attn_mma_kernel()
{
    extern __shared__ char dynsmem[];
    const uint32_t base_u = smem_u32(dynsmem);
    const uint32_t sQh = base_u;
    const uint32_t sQl = base_u + AQ_BY;
    const uint32_t kvb = base_u + 2 * AQ_BY;

    const int tid  = threadIdx.x;
    const int w    = tid >> 5, lane = tid & 31;
    const int bh   = blockIdx.y;
    const int qt   = (int)(gridDim.x - 1 - blockIdx.x);   // heavy tiles first
    const int q0   = qt * 128;
    const int nt   = 2 * qt + 2;

    const size_t hb = (size_t)bh * SS * DH;
    const __nv_bfloat16* qhp = g_qh + hb;
    const __nv_bfloat16* qlp = g_ql + hb;
    const __nv_bfloat16* khp = g_kh + hb;
    const __nv_bfloat16* klp = g_kl + hb;
    const __nv_bfloat16* vhp = g_vh + hb;
    const __nv_bfloat16* vlp = g_vl + hb;

    auto load_q = [&]() {
        #pragma unroll
        for (int it = 0; it < 4; ++it) {
            int idx = tid + it * 256;
            int row = idx >> 3, seg = idx & 7;
            CP_ASYNC16(sQh + row * AROWB + seg * 16, qhp + (size_t)(q0 + row) * DH + seg * 8);
            CP_ASYNC16(sQl + row * AROWB + seg * 16, qlp + (size_t)(q0 + row) * DH + seg * 8);
        }
    };
    auto issue_kv = [&](int kt, int st) {
        const int t0 = kt * 64;
        const __nv_bfloat16* srcs[4] = { khp, klp, vhp, vlp };
        uint32_t sb = kvb + st * ASTAGE_BY;
        #pragma unroll
        for (int tile = 0; tile < 4; ++tile) {
            const __nv_bfloat16* src = srcs[tile] + (size_t)t0 * DH;
            uint32_t dst = sb + tile * ATILE_BY;
            #pragma unroll
            for (int it = 0; it < 2; ++it) {
                int idx = tid + it * 256;
                int row = idx >> 3, seg = idx & 7;
                CP_ASYNC16(dst + row * AROWB + seg * 16, src + (size_t)row * DH + seg * 8);
            }
        }
    };

    load_q(); issue_kv(0, 0); CP_COMMIT();
    if (nt > 1) { issue_kv(1, 1); }
    CP_COMMIT();

    float Oa[8][4];
    #pragma unroll
    for (int i = 0; i < 8; ++i)
        #pragma unroll
        for (int j = 0; j < 4; ++j) Oa[i][j] = 0.f;
    float m_run0 = -1e30f, m_run1 = -1e30f, l_run0 = 0.f, l_run1 = 0.f;

    const uint32_t qoffA = (uint32_t)(16 * w + (lane & 15)) * AROWB + ((lane >> 4) & 1) * 16;
    const int krow = (lane & 7) + ((lane >> 4) & 1) * 8;
    const int kkof = ((lane >> 3) & 1) * 16;
    const int vrow = ((lane >> 3) & 1) * 8 + (lane & 7);
    const int vcof = ((lane >> 4) & 1) * 8;

    uint32_t qH[4][4];    // register-resident Qh fragments (all 4 k-steps)

    for (int kt = 0; kt < nt; ++kt) {
        const int st = kt & 1;
        const int t0 = kt * 64;
        if (kt + 1 < nt) CP_WAIT1(); else CP_WAIT0();
        __syncthreads();

        if (kt == 0) {
            #pragma unroll
            for (int ks = 0; ks < 4; ++ks)
                LDSM_X4(qH[ks][0], qH[ks][1], qH[ks][2], qH[ks][3], sQh + qoffA + ks * 32);
        }

        const uint32_t sK = kvb + st * ASTAGE_BY;
        const uint32_t sV = sK + 2 * ATILE_BY;

        // ---- S = Qh*Kh + Qh*Kl + Ql*Kh ----
        float acc[8][4];
        #pragma unroll
        for (int i = 0; i < 8; ++i)
            #pragma unroll
            for (int j = 0; j < 4; ++j) acc[i][j] = 0.f;

        #pragma unroll
        for (int ks = 0; ks < 4; ++ks) {
            uint32_t aL[4];
            LDSM_X4(aL[0], aL[1], aL[2], aL[3], sQl + qoffA + ks * 32);
            uint32_t kH[2][4], kL[2][4];
            {
                uint32_t kb = sK + (uint32_t)(krow) * AROWB + ks * 32 + kkof;
                LDSM_X4(kH[0][0], kH[0][1], kH[0][2], kH[0][3], kb);
                LDSM_X4(kL[0][0], kL[0][1], kL[0][2], kL[0][3], kb + ATILE_BY);
            }
            #pragma unroll
            for (int ng = 0; ng < 4; ++ng) {
                const int cur = ng & 1, nxt = cur ^ 1;
                if (ng < 3) {
                    uint32_t kb = sK + (uint32_t)(16 * (ng + 1) + krow) * AROWB + ks * 32 + kkof;
                    LDSM_X4(kH[nxt][0], kH[nxt][1], kH[nxt][2], kH[nxt][3], kb);
                    LDSM_X4(kL[nxt][0], kL[nxt][1], kL[nxt][2], kL[nxt][3], kb + ATILE_BY);
                }
                MMA16816(acc[2*ng],   qH[ks][0], qH[ks][1], qH[ks][2], qH[ks][3],
                         kH[cur][0], kH[cur][1]);
                MMA16816(acc[2*ng],   qH[ks][0], qH[ks][1], qH[ks][2], qH[ks][3],
                         kL[cur][0], kL[cur][1]);
                MMA16816(acc[2*ng],   aL[0], aL[1], aL[2], aL[3], kH[cur][0], kH[cur][1]);
                MMA16816(acc[2*ng+1], qH[ks][0], qH[ks][1], qH[ks][2], qH[ks][3],
                         kH[cur][2], kH[cur][3]);
                MMA16816(acc[2*ng+1], qH[ks][0], qH[ks][1], qH[ks][2], qH[ks][3],
                         kL[cur][2], kL[cur][3]);
                MMA16816(acc[2*ng+1], aL[0], aL[1], aL[2], aL[3], kH[cur][2], kH[cur][3]);
            }
        }

        // ---- causal mask (diagonal region only) ----
        if (kt >= 2 * qt) {
            int rb = q0 + 16 * w + (lane >> 2);
            int cb = t0 + 2 * (lane & 3);
            #pragma unroll
            for (int nf = 0; nf < 8; ++nf) {
                int c0 = cb + 8 * nf;
                if (c0     > rb)     acc[nf][0] = -1e30f;
                if (c0 + 1 > rb)     acc[nf][1] = -1e30f;
                if (c0     > rb + 8) acc[nf][2] = -1e30f;
                if (c0 + 1 > rb + 8) acc[nf][3] = -1e30f;
            }
        }

        // ---- online softmax (exp2 domain) ----
        float mx0 = -1e30f, mx1 = -1e30f;
        #pragma unroll
        for (int nf = 0; nf < 8; ++nf) {
            mx0 = fmaxf(mx0, fmaxf(acc[nf][0], acc[nf][1]));
            mx1 = fmaxf(mx1, fmaxf(acc[nf][2], acc[nf][3]));
        }
        mx0 = fmaxf(mx0, __shfl_xor_sync(0xffffffffu, mx0, 1));
        mx0 = fmaxf(mx0, __shfl_xor_sync(0xffffffffu, mx0, 2));
        mx1 = fmaxf(mx1, __shfl_xor_sync(0xffffffffu, mx1, 1));
        mx1 = fmaxf(mx1, __shfl_xor_sync(0xffffffffu, mx1, 2));

        float mn0 = fmaxf(m_run0, mx0), mn1 = fmaxf(m_run1, mx1);
        float corr0 = exp2f(m_run0 - mn0), corr1 = exp2f(m_run1 - mn1);

        uint32_t pH[8][2], pL[8][2];
        float s0 = 0.f, s1 = 0.f;
        #pragma unroll
        for (int nf = 0; nf < 8; ++nf) {
            float p00 = exp2f(acc[nf][0] - mn0);
            float p01 = exp2f(acc[nf][1] - mn0);
            float p10 = exp2f(acc[nf][2] - mn1);
            float p11 = exp2f(acc[nf][3] - mn1);
            s0 += p00 + p01; s1 += p10 + p11;
            __nv_bfloat16 h00 = __float2bfloat16(p00), h01 = __float2bfloat16(p01);
            __nv_bfloat16 h10 = __float2bfloat16(p10), h11 = __float2bfloat16(p11);
            pH[nf][0] = pack_bf2(h00, h01);
            pH[nf][1] = pack_bf2(h10, h11);
            pL[nf][0] = pack_bf2(__float2bfloat16(p00 - __bfloat162float(h00)),
                                 __float2bfloat16(p01 - __bfloat162float(h01)));
            pL[nf][1] = pack_bf2(__float2bfloat16(p10 - __bfloat162float(h10)),
                                 __float2bfloat16(p11 - __bfloat162float(h11)));
        }
        s0 += __shfl_xor_sync(0xffffffffu, s0, 1);
        s0 += __shfl_xor_sync(0xffffffffu, s0, 2);
        s1 += __shfl_xor_sync(0xffffffffu, s1, 1);
        s1 += __shfl_xor_sync(0xffffffffu, s1, 2);
        l_run0 = l_run0 * corr0 + s0;  m_run0 = mn0;
        l_run1 = l_run1 * corr1 + s1;  m_run1 = mn1;

        #pragma unroll
        for (int nf = 0; nf < 8; ++nf) {
            Oa[nf][0] *= corr0; Oa[nf][1] *= corr0;
            Oa[nf][2] *= corr1; Oa[nf][3] *= corr1;
        }

        // ---- O += Ph*Vh + Ph*Vl + Pl*Vh  (p-pipelined V loads) ----
        #pragma unroll
        for (int kc = 0; kc < 4; ++kc) {
            uint32_t aH0 = pH[2*kc][0],   aH1 = pH[2*kc][1];
            uint32_t aH2 = pH[2*kc+1][0], aH3 = pH[2*kc+1][1];
            uint32_t aL0 = pL[2*kc][0],   aL1 = pL[2*kc][1];
            uint32_t aL2 = pL[2*kc+1][0], aL3 = pL[2*kc+1][1];
            uint32_t vH[2][4], vL[2][4];
            {
                uint32_t va = sV + (uint32_t)(16 * kc + vrow) * AROWB + vcof * 2;
                LDSM_X4_T(vH[0][0], vH[0][1], vH[0][2], vH[0][3], va);
                LDSM_X4_T(vL[0][0], vL[0][1], vL[0][2], vL[0][3], va + ATILE_BY);
            }
            #pragma unroll
            for (int p = 0; p < 4; ++p) {
                const int cur = p & 1, nxt = cur ^ 1;
                if (p < 3) {
                    uint32_t va = sV + (uint32_t)(16 * kc + vrow) * AROWB
                                + (16 * (p + 1) + vcof) * 2;
                    LDSM_X4_T(vH[nxt][0], vH[nxt][1], vH[nxt][2], vH[nxt][3], va);
                    LDSM_X4_T(vL[nxt][0], vL[nxt][1], vL[nxt][2], vL[nxt][3], va + ATILE_BY);
                }
                MMA16816(Oa[2*p],   aH0, aH1, aH2, aH3, vH[cur][0], vH[cur][1]);
                MMA16816(Oa[2*p],   aH0, aH1, aH2, aH3, vL[cur][0], vL[cur][1]);
                MMA16816(Oa[2*p],   aL0, aL1, aL2, aL3, vH[cur][0], vH[cur][1]);
                MMA16816(Oa[2*p+1], aH0, aH1, aH2, aH3, vH[cur][2], vH[cur][3]);
                MMA16816(Oa[2*p+1], aH0, aH1, aH2, aH3, vL[cur][2], vL[cur][3]);
                MMA16816(Oa[2*p+1], aL0, aL1, aL2, aL3, vH[cur][2], vH[cur][3]);
            }
        }

        __syncthreads();
        if (kt + 2 < nt) { issue_kv(kt + 2, st); CP_COMMIT(); }
    }

    // ---- epilogue: write bf16 hi/lo into [M][D] for out projection ----
    float inv0 = 1.f / l_run0, inv1 = 1.f / l_run1;
    int b = bh >> 4, h = bh & (HH - 1);
    int r0 = q0 + 16 * w + (lane >> 2);
    size_t ro0 = (size_t)(b * SS + r0) * DD + h * DH;
    size_t ro1 = ro0 + (size_t)8 * DD;
    #pragma unroll
    for (int nf = 0; nf < 8; ++nf) {
        int d = 8 * nf + 2 * (lane & 3);
        float v00 = Oa[nf][0] * inv0, v01 = Oa[nf][1] * inv0;
        float v10 = Oa[nf][2] * inv1, v11 = Oa[nf][3] * inv1;
        __nv_bfloat16 h00 = __float2bfloat16(v00), h01 = __float2bfloat16(v01);
        __nv_bfloat16 h10 = __float2bfloat16(v10), h11 = __float2bfloat16(v11);
        *(uint32_t*)(g_at_hi + ro0 + d) = pack_bf2(h00, h01);
        *(uint32_t*)(g_at_hi + ro1 + d) = pack_bf2(h10, h11);
        *(uint32_t*)(g_at_lo + ro0 + d) = pack_bf2(
            __float2bfloat16(v00 - __bfloat162float(h00)),
            __float2bfloat16(v01 - __bfloat162float(h01)));
        *(uint32_t*)(g_at_lo + ro1 + d) = pack_bf2(
            __float2bfloat16(v10 - __bfloat162float(h10)),
            __float2bfloat16(v11 - __bfloat162float(h11)));
    }
}

// ---------------------------------------------------------------------------
extern "C" void kernel_launch(void* const* d_in, const int* in_sizes, int n_in,
                              void* d_out, int out_size)
{
    const float* x  = (const float*)d_in[0];
    const float* Wq = (const float*)d_in[1];
    const float* bq = (const float*)d_in[2];
    const float* Wk = (const float*)d_in[3];
    const float* bk = (const float*)d_in[4];
    const float* Wv = (const float*)d_in[5];
    const float* bv = (const float*)d_in[6];
    const float* Wo = (const float*)d_in[7];
    const float* bo = (const float*)d_in[8];
    float* out = (float*)d_out;

    cudaFuncSetAttribute(qkv_mma_kernel,
                         cudaFuncAttributeMaxDynamicSharedMemorySize, SMEM_MMA);
    cudaFuncSetAttribute(outproj_mma_kernel,
                         cudaFuncAttributeMaxDynamicSharedMemorySize, SMEM_MMA);
    cudaFuncSetAttribute(attn_mma_kernel,
                         cudaFuncAttributeMaxDynamicSharedMemorySize, SMEM_ATT);

    // 1) split x, transpose+split weights
    {
        __nv_bfloat16 *xh, *xl;
        cudaGetSymbolAddress((void**)&xh, g_x_hi);
        cudaGetSymbolAddress((void**)&xl, g_x_lo);
        split_kernel<<<(MROWS * DD) / (256 * 4), 256>>>(x, xh, xl);
        transpose_split_w<<<dim3(32, 32, 4), dim3(32, 8)>>>(Wq, Wk, Wv, Wo);
    }

    // 2) QKV projections (HMMA split-bf16, direct bf16 hi/lo epilogue)
    qkv_mma_kernel<<<dim3(DD / 128, MROWS / 128, 3), 256, SMEM_MMA>>>(bq, bk, bv);

    // 3) tensor-core causal flash attention
    attn_mma_kernel<<<dim3(SS / 128, BB * HH), 256, SMEM_ATT>>>();

    // 4) output projection
    outproj_mma_kernel<<<dim3(DD / 128, MROWS / 128), 256, SMEM_MMA>>>(bo, out);
}

// round 6
// speedup vs baseline: 1.0711x; 1.0711x over previous
#include <cuda_runtime.h>
#include <cuda_bf16.h>
#include <cstdint>
#include <math.h>
#include <string.h>

// Problem shape (fixed)
#define BB 4
#define SS 2048
#define DD 1024
#define HH 16
#define DH 64
#define MROWS (BB*SS)   // 8192

// ---------------------------------------------------------------------------
// Scratch (__device__ globals; allocation-free rule). All bf16 hi/lo pairs.
// q/k/v layout: [B*H][S][64]
// ---------------------------------------------------------------------------
__device__ __nv_bfloat16 g_qh[(size_t)BB*HH*SS*DH];
__device__ __nv_bfloat16 g_ql[(size_t)BB*HH*SS*DH];
__device__ __nv_bfloat16 g_kh[(size_t)BB*HH*SS*DH];
__device__ __nv_bfloat16 g_kl[(size_t)BB*HH*SS*DH];
__device__ __nv_bfloat16 g_vh[(size_t)BB*HH*SS*DH];
__device__ __nv_bfloat16 g_vl[(size_t)BB*HH*SS*DH];

__device__ __nv_bfloat16 g_x_hi[(size_t)MROWS*DD];
__device__ __nv_bfloat16 g_x_lo[(size_t)MROWS*DD];
__device__ __nv_bfloat16 g_at_hi[(size_t)MROWS*DD];
__device__ __nv_bfloat16 g_at_lo[(size_t)MROWS*DD];
// transposed+split weights: [4][N][K], Wt[n][k] = W[k][n]; 0..3 = q,k,v,o
__device__ __nv_bfloat16 g_wt_hi[(size_t)4*DD*DD];
__device__ __nv_bfloat16 g_wt_lo[(size_t)4*DD*DD];

// ---------------------------------------------------------------------------
// Helpers (base-sm_103-safe)
// ---------------------------------------------------------------------------
__device__ __forceinline__ uint32_t smem_u32(const void* p) {
    uint32_t a;
    asm("{ .reg .u64 t; cvta.to.shared.u64 t, %1; cvt.u32.u64 %0, t; }"
        : "=r"(a) : "l"(p));
    return a;
}
#define CP_ASYNC16(dst_u32, src_ptr) \
    asm volatile("cp.async.cg.shared.global [%0], [%1], 16;" \
                 :: "r"(dst_u32), "l"(src_ptr))
#define CP_COMMIT() asm volatile("cp.async.commit_group;")
#define CP_WAIT1()  asm volatile("cp.async.wait_group 1;")
#define CP_WAIT0()  asm volatile("cp.async.wait_group 0;")

#define LDSM_X4(r0, r1, r2, r3, addr) \
    asm volatile("ldmatrix.sync.aligned.m8n8.x4.shared.b16 {%0,%1,%2,%3}, [%4];" \
                 : "=r"(r0), "=r"(r1), "=r"(r2), "=r"(r3) : "r"(addr))
#define LDSM_X4_T(r0, r1, r2, r3, addr) \
    asm volatile("ldmatrix.sync.aligned.m8n8.x4.trans.shared.b16 {%0,%1,%2,%3}, [%4];" \
                 : "=r"(r0), "=r"(r1), "=r"(r2), "=r"(r3) : "r"(addr))

#define MMA16816(d, a0, a1, a2, a3, b0, b1) \
    asm volatile("mma.sync.aligned.m16n8k16.row.col.f32.bf16.bf16.f32 " \
                 "{%0,%1,%2,%3}, {%4,%5,%6,%7}, {%8,%9}, {%0,%1,%2,%3};" \
                 : "+f"((d)[0]), "+f"((d)[1]), "+f"((d)[2]), "+f"((d)[3]) \
                 : "r"(a0), "r"(a1), "r"(a2), "r"(a3), "r"(b0), "r"(b1))

__device__ __forceinline__ uint32_t pack_bf2(__nv_bfloat16 a, __nv_bfloat16 b) {
    __nv_bfloat162 h; h.x = a; h.y = b;
    uint32_t u; memcpy(&u, &h, 4);
    return u;
}

// q scale: (1/sqrt(64)) * log2(e), so softmax runs in exp2 domain
#define QSCALE 0.1803368801111204f

// ---------------------------------------------------------------------------
// Prep kernels
// ---------------------------------------------------------------------------
__global__ void __launch_bounds__(256)
split_kernel(const float* __restrict__ in, __nv_bfloat16* __restrict__ hi,
             __nv_bfloat16* __restrict__ lo) {
    size_t i = ((size_t)blockIdx.x * 256 + threadIdx.x) * 4;
    float4 v = *(const float4*)(in + i);
    __nv_bfloat16 h0 = __float2bfloat16(v.x);
    __nv_bfloat16 h1 = __float2bfloat16(v.y);
    __nv_bfloat16 h2 = __float2bfloat16(v.z);
    __nv_bfloat16 h3 = __float2bfloat16(v.w);
    *(uint32_t*)(hi + i)     = pack_bf2(h0, h1);
    *(uint32_t*)(hi + i + 2) = pack_bf2(h2, h3);
    *(uint32_t*)(lo + i)     = pack_bf2(__float2bfloat16(v.x - __bfloat162float(h0)),
                                        __float2bfloat16(v.y - __bfloat162float(h1)));
    *(uint32_t*)(lo + i + 2) = pack_bf2(__float2bfloat16(v.z - __bfloat162float(h2)),
                                        __float2bfloat16(v.w - __bfloat162float(h3)));
}

__global__ void __launch_bounds__(256)
transpose_split_w(const float* __restrict__ Wq, const float* __restrict__ Wk,
                  const float* __restrict__ Wv, const float* __restrict__ Wo) {
    __shared__ float t[32][33];
    const float* W = (blockIdx.z == 0) ? Wq : (blockIdx.z == 1) ? Wk :
                     (blockIdx.z == 2) ? Wv : Wo;
    __nv_bfloat16* Th = g_wt_hi + (size_t)blockIdx.z * DD * DD;
    __nv_bfloat16* Tl = g_wt_lo + (size_t)blockIdx.z * DD * DD;
    int k0 = blockIdx.y * 32, n0 = blockIdx.x * 32;
    int tx = threadIdx.x, ty = threadIdx.y;
    #pragma unroll
    for (int i = ty; i < 32; i += 8)
        t[i][tx] = W[(size_t)(k0 + i) * DD + n0 + tx];
    __syncthreads();
    #pragma unroll
    for (int i = ty; i < 32; i += 8) {
        float v = t[tx][i];
        size_t o = (size_t)(n0 + i) * DD + k0 + tx;
        __nv_bfloat16 h = __float2bfloat16(v);
        Th[o] = h;
        Tl[o] = __float2bfloat16(v - __bfloat162float(h));
    }
}

// ---------------------------------------------------------------------------
// Split-bf16 GEMM on mma.sync. 128x128 CTA tile, 4 warps (2x2), warp tile
// 64x64 -> MMA:LDSM ratio 6:1. 128 threads. 2-stage cp.async pipeline.
// MODE 0: fp32 out [M][N]. MODE 1: bf16 hi/lo split-scatter to [B*H][S][64].
// ---------------------------------------------------------------------------
#define KC 32
#define NCHUNK (DD / KC)              // 32
#define ROW_B 80
#define TILE_BY (128 * ROW_B)
#define STAGE_BY (4 * TILE_BY)
#define SMEM_MMA (2 * STAGE_BY)       // 81920
#define GT 128                        // GEMM threads

template<int MODE>
__device__ __forceinline__ void mma_gemm_body(const __nv_bfloat16* __restrict__ Ah,
                                              const __nv_bfloat16* __restrict__ Al,
                                              const __nv_bfloat16* __restrict__ Bh,
                                              const __nv_bfloat16* __restrict__ Bl,
                                              const float* __restrict__ bias,
                                              float* __restrict__ C,
                                              __nv_bfloat16* __restrict__ Hi,
                                              __nv_bfloat16* __restrict__ Lo,
                                              float scale)
{
    extern __shared__ char dynsmem[];
    const uint32_t base_u = smem_u32(dynsmem);

    const int tid  = threadIdx.x;
    const int wid  = tid >> 5, lane = tid & 31;
    const int wm   = wid & 1;          // M half
    const int wn   = wid >> 1;         // N half
    const int m0   = blockIdx.y * 128;
    const int n0   = blockIdx.x * 128;

    const __nv_bfloat16* srcs[4] = { Ah, Al, Bh, Bl };
    const int rowbase[4] = { m0, m0, n0, n0 };

    auto issue_stage = [&](int c, int st) {
        #pragma unroll
        for (int tile = 0; tile < 4; ++tile) {
            const __nv_bfloat16* src = srcs[tile] + (size_t)rowbase[tile] * DD + c * KC;
            uint32_t dst = base_u + st * STAGE_BY + tile * TILE_BY;
            #pragma unroll
            for (int it = 0; it < 4; ++it) {
                int idx = tid + it * GT;           // 0..511
                int row = idx >> 2;
                int seg = idx & 3;
                CP_ASYNC16(dst + row * ROW_B + seg * 16,
                           src + (size_t)row * DD + seg * 8);
            }
        }
    };

    float acc[4][8][4];
    #pragma unroll
    for (int i = 0; i < 4; ++i)
        #pragma unroll
        for (int j = 0; j < 8; ++j)
            #pragma unroll
            for (int q = 0; q < 4; ++q) acc[i][j][q] = 0.f;

    const int arow = wm * 64 + (lane & 15);            // + mf*16
    const int akof = ((lane >> 4) & 1) * 16;
    const int brow = wn * 64 + (lane & 7) + ((lane >> 4) & 1) * 8;   // + ng*16
    const int bkof = ((lane >> 3) & 1) * 16;

    issue_stage(0, 0); CP_COMMIT();
    issue_stage(1, 1); CP_COMMIT();

    for (int c = 0; c < NCHUNK; ++c) {
        const int st = c & 1;
        if (c + 2 < NCHUNK) CP_WAIT1(); else CP_WAIT0();
        __syncthreads();

        const uint32_t sA_hi = base_u + st * STAGE_BY;
        const uint32_t sA_lo = sA_hi + TILE_BY;
        const uint32_t sB_hi = sA_hi + 2 * TILE_BY;
        const uint32_t sB_lo = sA_hi + 3 * TILE_BY;

        #pragma unroll
        for (int ks = 0; ks < 2; ++ks) {
            uint32_t ah[4][4], al[4][4];
            #pragma unroll
            for (int mf = 0; mf < 4; ++mf) {
                uint32_t ra = (arow + mf * 16) * ROW_B + ks * 32 + akof;
                LDSM_X4(ah[mf][0], ah[mf][1], ah[mf][2], ah[mf][3], sA_hi + ra);
                LDSM_X4(al[mf][0], al[mf][1], al[mf][2], al[mf][3], sA_lo + ra);
            }
            #pragma unroll
            for (int ng = 0; ng < 4; ++ng) {
                uint32_t bh[4], bl[4];
                uint32_t rb = (brow + ng * 16) * ROW_B + ks * 32 + bkof;
                LDSM_X4(bh[0], bh[1], bh[2], bh[3], sB_hi + rb);
                LDSM_X4(bl[0], bl[1], bl[2], bl[3], sB_lo + rb);
                #pragma unroll
                for (int mf = 0; mf < 4; ++mf) {
                    MMA16816(acc[mf][2*ng],   ah[mf][0], ah[mf][1], ah[mf][2], ah[mf][3],
                             bh[0], bh[1]);
                    MMA16816(acc[mf][2*ng],   ah[mf][0], ah[mf][1], ah[mf][2], ah[mf][3],
                             bl[0], bl[1]);
                    MMA16816(acc[mf][2*ng],   al[mf][0], al[mf][1], al[mf][2], al[mf][3],
                             bh[0], bh[1]);
                    MMA16816(acc[mf][2*ng+1], ah[mf][0], ah[mf][1], ah[mf][2], ah[mf][3],
                             bh[2], bh[3]);
                    MMA16816(acc[mf][2*ng+1], ah[mf][0], ah[mf][1], ah[mf][2], ah[mf][3],
                             bl[2], bl[3]);
                    MMA16816(acc[mf][2*ng+1], al[mf][0], al[mf][1], al[mf][2], al[mf][3],
                             bh[2], bh[3]);
                }
            }
        }
        __syncthreads();
        if (c + 2 < NCHUNK) { issue_stage(c + 2, st); CP_COMMIT(); }
    }

    const int mrow = lane >> 2;
    const int ncol = (lane & 3) * 2;
    #pragma unroll
    for (int mf = 0; mf < 4; ++mf) {
        #pragma unroll
        for (int nf = 0; nf < 8; ++nf) {
            int m = m0 + wm * 64 + mf * 16 + mrow;
            int n = n0 + wn * 64 + nf * 8 + ncol;
            float b0 = bias[n], b1 = bias[n + 1];
            float v00 = (acc[mf][nf][0] + b0) * scale;
            float v01 = (acc[mf][nf][1] + b1) * scale;
            float v10 = (acc[mf][nf][2] + b0) * scale;
            float v11 = (acc[mf][nf][3] + b1) * scale;
            if (MODE == 0) {
                *(float2*)&C[(size_t)m * DD + n]       = make_float2(v00, v01);
                *(float2*)&C[(size_t)(m + 8) * DD + n] = make_float2(v10, v11);
            } else {
                int b = m >> 11, h = n >> 6, d = n & 63;
                int s  = m & (SS - 1);
                size_t o0 = (((size_t)(b * HH + h)) * SS + s) * DH + d;
                size_t o1 = o0 + 8 * DH;
                __nv_bfloat16 h00 = __float2bfloat16(v00), h01 = __float2bfloat16(v01);
                __nv_bfloat16 h10 = __float2bfloat16(v10), h11 = __float2bfloat16(v11);
                *(uint32_t*)(Hi + o0) = pack_bf2(h00, h01);
                *(uint32_t*)(Hi + o1) = pack_bf2(h10, h11);
                *(uint32_t*)(Lo + o0) = pack_bf2(
                    __float2bfloat16(v00 - __bfloat162float(h00)),
                    __float2bfloat16(v01 - __bfloat162float(h01)));
                *(uint32_t*)(Lo + o1) = pack_bf2(
                    __float2bfloat16(v10 - __bfloat162float(h10)),
                    __float2bfloat16(v11 - __bfloat162float(h11)));
            }
        }
    }
}

__global__ void __launch_bounds__(GT)
qkv_mma_kernel(const float* __restrict__ bq, const float* __restrict__ bk,
               const float* __restrict__ bv) {
    int z = blockIdx.z;
    __nv_bfloat16* Hi = (z == 0) ? g_qh : (z == 1) ? g_kh : g_vh;
    __nv_bfloat16* Lo = (z == 0) ? g_ql : (z == 1) ? g_kl : g_vl;
    const float* bias = (z == 0) ? bq : (z == 1) ? bk : bv;
    float scale = (z == 0) ? QSCALE : 1.0f;
    mma_gemm_body<1>(g_x_hi, g_x_lo,
                     g_wt_hi + (size_t)z * DD * DD, g_wt_lo + (size_t)z * DD * DD,
                     bias, nullptr, Hi, Lo, scale);
}

__global__ void __launch_bounds__(GT)
outproj_mma_kernel(const float* __restrict__ bo, float* __restrict__ out) {
    mma_gemm_body<0>(g_at_hi, g_at_lo,
                     g_wt_hi + (size_t)3 * DD * DD, g_wt_lo + (size_t)3 * DD * DD,
                     bo, out, nullptr, nullptr, 1.0f);
}

// ---------------------------------------------------------------------------
// Tensor-core flash attention (split-bf16, causal, exp2 domain).
// R4 structure (measured best): CTA 128 Q x 64 KV, 8 warps, 256 threads.
// ---------------------------------------------------------------------------
#define AROWB 144
#define ATILE_BY (64 * AROWB)
#define AQ_BY (128 * AROWB)
#define ASTAGE_BY (4 * ATILE_BY)
#define SMEM_ATT (2 * AQ_BY + 2 * ASTAGE_BY)   // 110592

__global__ void __launch_bounds__(256, 2)
attn_mma_kernel()
{
    extern __shared__ char dynsmem[];
    const uint32_t base_u = smem_u32(dynsmem);
    const uint32_t sQh = base_u;
    const uint32_t sQl = base_u + AQ_BY;
    const uint32_t kvb = base_u + 2 * AQ_BY;

    const int tid  = threadIdx.x;
    const int w    = tid >> 5, lane = tid & 31;
    const int bh   = blockIdx.y;
    const int qt   = (int)(gridDim.x - 1 - blockIdx.x);   // heavy tiles first
    const int q0   = qt * 128;
    const int nt   = 2 * qt + 2;

    const size_t hb = (size_t)bh * SS * DH;
    const __nv_bfloat16* qhp = g_qh + hb;
    const __nv_bfloat16* qlp = g_ql + hb;
    const __nv_bfloat16* khp = g_kh + hb;
    const __nv_bfloat16* klp = g_kl + hb;
    const __nv_bfloat16* vhp = g_vh + hb;
    const __nv_bfloat16* vlp = g_vl + hb;

    auto load_q = [&]() {
        #pragma unroll
        for (int it = 0; it < 4; ++it) {
            int idx = tid + it * 256;
            int row = idx >> 3, seg = idx & 7;
            CP_ASYNC16(sQh + row * AROWB + seg * 16, qhp + (size_t)(q0 + row) * DH + seg * 8);
            CP_ASYNC16(sQl + row * AROWB + seg * 16, qlp + (size_t)(q0 + row) * DH + seg * 8);
        }
    };
    auto issue_kv = [&](int kt, int st) {
        const int t0 = kt * 64;
        const __nv_bfloat16* srcs[4] = { khp, klp, vhp, vlp };
        uint32_t sb = kvb + st * ASTAGE_BY;
        #pragma unroll
        for (int tile = 0; tile < 4; ++tile) {
            const __nv_bfloat16* src = srcs[tile] + (size_t)t0 * DH;
            uint32_t dst = sb + tile * ATILE_BY;
            #pragma unroll
            for (int it = 0; it < 2; ++it) {
                int idx = tid + it * 256;
                int row = idx >> 3, seg = idx & 7;
                CP_ASYNC16(dst + row * AROWB + seg * 16, src + (size_t)row * DH + seg * 8);
            }
        }
    };

    load_q(); issue_kv(0, 0); CP_COMMIT();
    if (nt > 1) { issue_kv(1, 1); }
    CP_COMMIT();

    float Oa[8][4];
    #pragma unroll
    for (int i = 0; i < 8; ++i)
        #pragma unroll
        for (int j = 0; j < 4; ++j) Oa[i][j] = 0.f;
    float m_run0 = -1e30f, m_run1 = -1e30f, l_run0 = 0.f, l_run1 = 0.f;

    const uint32_t qoffA = (uint32_t)(16 * w + (lane & 15)) * AROWB + ((lane >> 4) & 1) * 16;
    const int krow = (lane & 7) + ((lane >> 4) & 1) * 8;
    const int kkof = ((lane >> 3) & 1) * 16;
    const int vrow = ((lane >> 3) & 1) * 8 + (lane & 7);
    const int vcof = ((lane >> 4) & 1) * 8;

    for (int kt = 0; kt < nt; ++kt) {
        const int st = kt & 1;
        const int t0 = kt * 64;
        if (kt + 1 < nt) CP_WAIT1(); else CP_WAIT0();
        __syncthreads();

        const uint32_t sK = kvb + st * ASTAGE_BY;
        const uint32_t sV = sK + 2 * ATILE_BY;

        // ---- S = Qh*Kh + Qh*Kl + Ql*Kh ----
        float acc[8][4];
        #pragma unroll
        for (int i = 0; i < 8; ++i)
            #pragma unroll
            for (int j = 0; j < 4; ++j) acc[i][j] = 0.f;

        #pragma unroll
        for (int ks = 0; ks < 4; ++ks) {
            uint32_t qa = qoffA + ks * 32;
            uint32_t aH[4], aL[4];
            LDSM_X4(aH[0], aH[1], aH[2], aH[3], sQh + qa);
            LDSM_X4(aL[0], aL[1], aL[2], aL[3], sQl + qa);
            #pragma unroll
            for (int ng = 0; ng < 4; ++ng) {
                uint32_t kb = sK + (uint32_t)(16 * ng + krow) * AROWB + ks * 32 + kkof;
                uint32_t kH[4], kL[4];
                LDSM_X4(kH[0], kH[1], kH[2], kH[3], kb);
                LDSM_X4(kL[0], kL[1], kL[2], kL[3], kb + ATILE_BY);
                MMA16816(acc[2*ng],   aH[0], aH[1], aH[2], aH[3], kH[0], kH[1]);
                MMA16816(acc[2*ng],   aH[0], aH[1], aH[2], aH[3], kL[0], kL[1]);
                MMA16816(acc[2*ng],   aL[0], aL[1], aL[2], aL[3], kH[0], kH[1]);
                MMA16816(acc[2*ng+1], aH[0], aH[1], aH[2], aH[3], kH[2], kH[3]);
                MMA16816(acc[2*ng+1], aH[0], aH[1], aH[2], aH[3], kL[2], kL[3]);
                MMA16816(acc[2*ng+1], aL[0], aL[1], aL[2], aL[3], kH[2], kH[3]);
            }
        }

        // ---- causal mask (diagonal region only) ----
        if (kt >= 2 * qt) {
            int rb = q0 + 16 * w + (lane >> 2);
            int cb = t0 + 2 * (lane & 3);
            #pragma unroll
            for (int nf = 0; nf < 8; ++nf) {
                int c0 = cb + 8 * nf;
                if (c0     > rb)     acc[nf][0] = -1e30f;
                if (c0 + 1 > rb)     acc[nf][1] = -1e30f;
                if (c0     > rb + 8) acc[nf][2] = -1e30f;
                if (c0 + 1 > rb + 8) acc[nf][3] = -1e30f;
            }
        }

        // ---- online softmax (exp2 domain) ----
        float mx0 = -1e30f, mx1 = -1e30f;
        #pragma unroll
        for (int nf = 0; nf < 8; ++nf) {
            mx0 = fmaxf(mx0, fmaxf(acc[nf][0], acc[nf][1]));
            mx1 = fmaxf(mx1, fmaxf(acc[nf][2], acc[nf][3]));
        }
        mx0 = fmaxf(mx0, __shfl_xor_sync(0xffffffffu, mx0, 1));
        mx0 = fmaxf(mx0, __shfl_xor_sync(0xffffffffu, mx0, 2));
        mx1 = fmaxf(mx1, __shfl_xor_sync(0xffffffffu, mx1, 1));
        mx1 = fmaxf(mx1, __shfl_xor_sync(0xffffffffu, mx1, 2));

        float mn0 = fmaxf(m_run0, mx0), mn1 = fmaxf(m_run1, mx1);
        float corr0 = exp2f(m_run0 - mn0), corr1 = exp2f(m_run1 - mn1);

        uint32_t pH[8][2], pL[8][2];
        float s0 = 0.f, s1 = 0.f;
        #pragma unroll
        for (int nf = 0; nf < 8; ++nf) {
            float p00 = exp2f(acc[nf][0] - mn0);
            float p01 = exp2f(acc[nf][1] - mn0);
            float p10 = exp2f(acc[nf][2] - mn1);
            float p11 = exp2f(acc[nf][3] - mn1);
            s0 += p00 + p01; s1 += p10 + p11;
            __nv_bfloat16 h00 = __float2bfloat16(p00), h01 = __float2bfloat16(p01);
            __nv_bfloat16 h10 = __float2bfloat16(p10), h11 = __float2bfloat16(p11);
            pH[nf][0] = pack_bf2(h00, h01);
            pH[nf][1] = pack_bf2(h10, h11);
            pL[nf][0] = pack_bf2(__float2bfloat16(p00 - __bfloat162float(h00)),
                                 __float2bfloat16(p01 - __bfloat162float(h01)));
            pL[nf][1] = pack_bf2(__float2bfloat16(p10 - __bfloat162float(h10)),
                                 __float2bfloat16(p11 - __bfloat162float(h11)));
        }
        s0 += __shfl_xor_sync(0xffffffffu, s0, 1);
        s0 += __shfl_xor_sync(0xffffffffu, s0, 2);
        s1 += __shfl_xor_sync(0xffffffffu, s1, 1);
        s1 += __shfl_xor_sync(0xffffffffu, s1, 2);
        l_run0 = l_run0 * corr0 + s0;  m_run0 = mn0;
        l_run1 = l_run1 * corr1 + s1;  m_run1 = mn1;

        #pragma unroll
        for (int nf = 0; nf < 8; ++nf) {
            Oa[nf][0] *= corr0; Oa[nf][1] *= corr0;
            Oa[nf][2] *= corr1; Oa[nf][3] *= corr1;
        }

        // ---- O += Ph*Vh + Ph*Vl + Pl*Vh ----
        #pragma unroll
        for (int kc = 0; kc < 4; ++kc) {
            uint32_t aH0 = pH[2*kc][0],   aH1 = pH[2*kc][1];
            uint32_t aH2 = pH[2*kc+1][0], aH3 = pH[2*kc+1][1];
            uint32_t aL0 = pL[2*kc][0],   aL1 = pL[2*kc][1];
            uint32_t aL2 = pL[2*kc+1][0], aL3 = pL[2*kc+1][1];
            #pragma unroll
            for (int p = 0; p < 4; ++p) {
                uint32_t va = sV + (uint32_t)(16 * kc + vrow) * AROWB + (16 * p + vcof) * 2;
                uint32_t vH[4], vL[4];
                LDSM_X4_T(vH[0], vH[1], vH[2], vH[3], va);
                LDSM_X4_T(vL[0], vL[1], vL[2], vL[3], va + ATILE_BY);
                MMA16816(Oa[2*p],   aH0, aH1, aH2, aH3, vH[0], vH[1]);
                MMA16816(Oa[2*p],   aH0, aH1, aH2, aH3, vL[0], vL[1]);
                MMA16816(Oa[2*p],   aL0, aL1, aL2, aL3, vH[0], vH[1]);
                MMA16816(Oa[2*p+1], aH0, aH1, aH2, aH3, vH[2], vH[3]);
                MMA16816(Oa[2*p+1], aH0, aH1, aH2, aH3, vL[2], vL[3]);
                MMA16816(Oa[2*p+1], aL0, aL1, aL2, aL3, vH[2], vH[3]);
            }
        }

        __syncthreads();
        if (kt + 2 < nt) { issue_kv(kt + 2, st); CP_COMMIT(); }
    }

    // ---- epilogue: write bf16 hi/lo into [M][D] for out projection ----
    float inv0 = 1.f / l_run0, inv1 = 1.f / l_run1;
    int b = bh >> 4, h = bh & (HH - 1);
    int r0 = q0 + 16 * w + (lane >> 2);
    size_t ro0 = (size_t)(b * SS + r0) * DD + h * DH;
    size_t ro1 = ro0 + (size_t)8 * DD;
    #pragma unroll
    for (int nf = 0; nf < 8; ++nf) {
        int d = 8 * nf + 2 * (lane & 3);
        float v00 = Oa[nf][0] * inv0, v01 = Oa[nf][1] * inv0;
        float v10 = Oa[nf][2] * inv1, v11 = Oa[nf][3] * inv1;
        __nv_bfloat16 h00 = __float2bfloat16(v00), h01 = __float2bfloat16(v01);
        __nv_bfloat16 h10 = __float2bfloat16(v10), h11 = __float2bfloat16(v11);
        *(uint32_t*)(g_at_hi + ro0 + d) = pack_bf2(h00, h01);
        *(uint32_t*)(g_at_hi + ro1 + d) = pack_bf2(h10, h11);
        *(uint32_t*)(g_at_lo + ro0 + d) = pack_bf2(
            __float2bfloat16(v00 - __bfloat162float(h00)),
            __float2bfloat16(v01 - __bfloat162float(h01)));
        *(uint32_t*)(g_at_lo + ro1 + d) = pack_bf2(
            __float2bfloat16(v10 - __bfloat162float(h10)),
            __float2bfloat16(v11 - __bfloat162float(h11)));
    }
}

// ---------------------------------------------------------------------------
extern "C" void kernel_launch(void* const* d_in, const int* in_sizes, int n_in,
                              void* d_out, int out_size)
{
    const float* x  = (const float*)d_in[0];
    const float* Wq = (const float*)d_in[1];
    const float* bq = (const float*)d_in[2];
    const float* Wk = (const float*)d_in[3];
    const float* bk = (const float*)d_in[4];
    const float* Wv = (const float*)d_in[5];
    const float* bv = (const float*)d_in[6];
    const float* Wo = (const float*)d_in[7];
    const float* bo = (const float*)d_in[8];
    float* out = (float*)d_out;

    cudaFuncSetAttribute(qkv_mma_kernel,
                         cudaFuncAttributeMaxDynamicSharedMemorySize, SMEM_MMA);
    cudaFuncSetAttribute(outproj_mma_kernel,
                         cudaFuncAttributeMaxDynamicSharedMemorySize, SMEM_MMA);
    cudaFuncSetAttribute(attn_mma_kernel,
                         cudaFuncAttributeMaxDynamicSharedMemorySize, SMEM_ATT);

    // 1) split x, transpose+split weights
    {
        __nv_bfloat16 *xh, *xl;
        cudaGetSymbolAddress((void**)&xh, g_x_hi);
        cudaGetSymbolAddress((void**)&xl, g_x_lo);
        split_kernel<<<(MROWS * DD) / (256 * 4), 256>>>(x, xh, xl);
        transpose_split_w<<<dim3(32, 32, 4), dim3(32, 8)>>>(Wq, Wk, Wv, Wo);
    }

    // 2) QKV projections (HMMA split-bf16, 64x64 warp tiles)
    qkv_mma_kernel<<<dim3(DD / 128, MROWS / 128, 3), GT, SMEM_MMA>>>(bq, bk, bv);

    // 3) tensor-core causal flash attention
    attn_mma_kernel<<<dim3(SS / 128, BB * HH), 256, SMEM_ATT>>>();

    // 4) output projection
    outproj_mma_kernel<<<dim3(DD / 128, MROWS / 128), GT, SMEM_MMA>>>(bo, out);
}

// round 7
// speedup vs baseline: 1.0855x; 1.0134x over previous
#include <cuda_runtime.h>
#include <cuda_bf16.h>
#include <cstdint>
#include <math.h>
#include <string.h>

// Problem shape (fixed)
#define BB 4
#define SS 2048
#define DD 1024
#define HH 16
#define DH 64
#define MROWS (BB*SS)   // 8192

// ---------------------------------------------------------------------------
// Scratch (__device__ globals; allocation-free rule). All bf16 hi/lo pairs.
// q/k/v layout: [B*H][S][64]
// ---------------------------------------------------------------------------
__device__ __nv_bfloat16 g_qh[(size_t)BB*HH*SS*DH];
__device__ __nv_bfloat16 g_ql[(size_t)BB*HH*SS*DH];
__device__ __nv_bfloat16 g_kh[(size_t)BB*HH*SS*DH];
__device__ __nv_bfloat16 g_kl[(size_t)BB*HH*SS*DH];
__device__ __nv_bfloat16 g_vh[(size_t)BB*HH*SS*DH];
__device__ __nv_bfloat16 g_vl[(size_t)BB*HH*SS*DH];

__device__ __nv_bfloat16 g_x_hi[(size_t)MROWS*DD];
__device__ __nv_bfloat16 g_x_lo[(size_t)MROWS*DD];
__device__ __nv_bfloat16 g_at_hi[(size_t)MROWS*DD];
__device__ __nv_bfloat16 g_at_lo[(size_t)MROWS*DD];
// transposed+split weights: [4][N][K], Wt[n][k] = W[k][n]; 0..3 = q,k,v,o
__device__ __nv_bfloat16 g_wt_hi[(size_t)4*DD*DD];
__device__ __nv_bfloat16 g_wt_lo[(size_t)4*DD*DD];

// ---------------------------------------------------------------------------
// Helpers (base-sm_103-safe)
// ---------------------------------------------------------------------------
__device__ __forceinline__ uint32_t smem_u32(const void* p) {
    uint32_t a;
    asm("{ .reg .u64 t; cvta.to.shared.u64 t, %1; cvt.u32.u64 %0, t; }"
        : "=r"(a) : "l"(p));
    return a;
}
#define CP_ASYNC16(dst_u32, src_ptr) \
    asm volatile("cp.async.cg.shared.global [%0], [%1], 16;" \
                 :: "r"(dst_u32), "l"(src_ptr))
#define CP_COMMIT() asm volatile("cp.async.commit_group;")
#define CP_WAIT1()  asm volatile("cp.async.wait_group 1;")
#define CP_WAIT0()  asm volatile("cp.async.wait_group 0;")

#define LDSM_X4(r0, r1, r2, r3, addr) \
    asm volatile("ldmatrix.sync.aligned.m8n8.x4.shared.b16 {%0,%1,%2,%3}, [%4];" \
                 : "=r"(r0), "=r"(r1), "=r"(r2), "=r"(r3) : "r"(addr))
#define LDSM_X4_T(r0, r1, r2, r3, addr) \
    asm volatile("ldmatrix.sync.aligned.m8n8.x4.trans.shared.b16 {%0,%1,%2,%3}, [%4];" \
                 : "=r"(r0), "=r"(r1), "=r"(r2), "=r"(r3) : "r"(addr))

#define MMA16816(d, a0, a1, a2, a3, b0, b1) \
    asm volatile("mma.sync.aligned.m16n8k16.row.col.f32.bf16.bf16.f32 " \
                 "{%0,%1,%2,%3}, {%4,%5,%6,%7}, {%8,%9}, {%0,%1,%2,%3};" \
                 : "+f"((d)[0]), "+f"((d)[1]), "+f"((d)[2]), "+f"((d)[3]) \
                 : "r"(a0), "r"(a1), "r"(a2), "r"(a3), "r"(b0), "r"(b1))

__device__ __forceinline__ uint32_t pack_bf2(__nv_bfloat16 a, __nv_bfloat16 b) {
    __nv_bfloat162 h; h.x = a; h.y = b;
    uint32_t u; memcpy(&u, &h, 4);
    return u;
}

// q scale: (1/sqrt(64)) * log2(e), so softmax runs in exp2 domain
#define QSCALE 0.1803368801111204f

// ---------------------------------------------------------------------------
// Prep kernels
// ---------------------------------------------------------------------------
__global__ void __launch_bounds__(256)
split_kernel(const float* __restrict__ in, __nv_bfloat16* __restrict__ hi,
             __nv_bfloat16* __restrict__ lo) {
    size_t i = ((size_t)blockIdx.x * 256 + threadIdx.x) * 4;
    float4 v = *(const float4*)(in + i);
    __nv_bfloat16 h0 = __float2bfloat16(v.x);
    __nv_bfloat16 h1 = __float2bfloat16(v.y);
    __nv_bfloat16 h2 = __float2bfloat16(v.z);
    __nv_bfloat16 h3 = __float2bfloat16(v.w);
    *(uint32_t*)(hi + i)     = pack_bf2(h0, h1);
    *(uint32_t*)(hi + i + 2) = pack_bf2(h2, h3);
    *(uint32_t*)(lo + i)     = pack_bf2(__float2bfloat16(v.x - __bfloat162float(h0)),
                                        __float2bfloat16(v.y - __bfloat162float(h1)));
    *(uint32_t*)(lo + i + 2) = pack_bf2(__float2bfloat16(v.z - __bfloat162float(h2)),
                                        __float2bfloat16(v.w - __bfloat162float(h3)));
}

__global__ void __launch_bounds__(256)
transpose_split_w(const float* __restrict__ Wq, const float* __restrict__ Wk,
                  const float* __restrict__ Wv, const float* __restrict__ Wo) {
    __shared__ float t[32][33];
    const float* W = (blockIdx.z == 0) ? Wq : (blockIdx.z == 1) ? Wk :
                     (blockIdx.z == 2) ? Wv : Wo;
    __nv_bfloat16* Th = g_wt_hi + (size_t)blockIdx.z * DD * DD;
    __nv_bfloat16* Tl = g_wt_lo + (size_t)blockIdx.z * DD * DD;
    int k0 = blockIdx.y * 32, n0 = blockIdx.x * 32;
    int tx = threadIdx.x, ty = threadIdx.y;
    #pragma unroll
    for (int i = ty; i < 32; i += 8)
        t[i][tx] = W[(size_t)(k0 + i) * DD + n0 + tx];
    __syncthreads();
    #pragma unroll
    for (int i = ty; i < 32; i += 8) {
        float v = t[tx][i];
        size_t o = (size_t)(n0 + i) * DD + k0 + tx;
        __nv_bfloat16 h = __float2bfloat16(v);
        Th[o] = h;
        Tl[o] = __float2bfloat16(v - __bfloat162float(h));
    }
}

// ---------------------------------------------------------------------------
// Split-bf16 GEMM on mma.sync (unchanged from R6 - measured good).
// 128x128 CTA tile, 4 warps (2x2), warp tile 64x64, 128 threads.
// ---------------------------------------------------------------------------
#define KC 32
#define NCHUNK (DD / KC)              // 32
#define ROW_B 80
#define TILE_BY (128 * ROW_B)
#define STAGE_BY (4 * TILE_BY)
#define SMEM_MMA (2 * STAGE_BY)       // 81920
#define GT 128                        // GEMM threads

template<int MODE>
__device__ __forceinline__ void mma_gemm_body(const __nv_bfloat16* __restrict__ Ah,
                                              const __nv_bfloat16* __restrict__ Al,
                                              const __nv_bfloat16* __restrict__ Bh,
                                              const __nv_bfloat16* __restrict__ Bl,
                                              const float* __restrict__ bias,
                                              float* __restrict__ C,
                                              __nv_bfloat16* __restrict__ Hi,
                                              __nv_bfloat16* __restrict__ Lo,
                                              float scale)
{
    extern __shared__ char dynsmem[];
    const uint32_t base_u = smem_u32(dynsmem);

    const int tid  = threadIdx.x;
    const int wid  = tid >> 5, lane = tid & 31;
    const int wm   = wid & 1;
    const int wn   = wid >> 1;
    const int m0   = blockIdx.y * 128;
    const int n0   = blockIdx.x * 128;

    const __nv_bfloat16* srcs[4] = { Ah, Al, Bh, Bl };
    const int rowbase[4] = { m0, m0, n0, n0 };

    auto issue_stage = [&](int c, int st) {
        #pragma unroll
        for (int tile = 0; tile < 4; ++tile) {
            const __nv_bfloat16* src = srcs[tile] + (size_t)rowbase[tile] * DD + c * KC;
            uint32_t dst = base_u + st * STAGE_BY + tile * TILE_BY;
            #pragma unroll
            for (int it = 0; it < 4; ++it) {
                int idx = tid + it * GT;
                int row = idx >> 2;
                int seg = idx & 3;
                CP_ASYNC16(dst + row * ROW_B + seg * 16,
                           src + (size_t)row * DD + seg * 8);
            }
        }
    };

    float acc[4][8][4];
    #pragma unroll
    for (int i = 0; i < 4; ++i)
        #pragma unroll
        for (int j = 0; j < 8; ++j)
            #pragma unroll
            for (int q = 0; q < 4; ++q) acc[i][j][q] = 0.f;

    const int arow = wm * 64 + (lane & 15);
    const int akof = ((lane >> 4) & 1) * 16;
    const int brow = wn * 64 + (lane & 7) + ((lane >> 4) & 1) * 8;
    const int bkof = ((lane >> 3) & 1) * 16;

    issue_stage(0, 0); CP_COMMIT();
    issue_stage(1, 1); CP_COMMIT();

    for (int c = 0; c < NCHUNK; ++c) {
        const int st = c & 1;
        if (c + 2 < NCHUNK) CP_WAIT1(); else CP_WAIT0();
        __syncthreads();

        const uint32_t sA_hi = base_u + st * STAGE_BY;
        const uint32_t sA_lo = sA_hi + TILE_BY;
        const uint32_t sB_hi = sA_hi + 2 * TILE_BY;
        const uint32_t sB_lo = sA_hi + 3 * TILE_BY;

        #pragma unroll
        for (int ks = 0; ks < 2; ++ks) {
            uint32_t ah[4][4], al[4][4];
            #pragma unroll
            for (int mf = 0; mf < 4; ++mf) {
                uint32_t ra = (arow + mf * 16) * ROW_B + ks * 32 + akof;
                LDSM_X4(ah[mf][0], ah[mf][1], ah[mf][2], ah[mf][3], sA_hi + ra);
                LDSM_X4(al[mf][0], al[mf][1], al[mf][2], al[mf][3], sA_lo + ra);
            }
            #pragma unroll
            for (int ng = 0; ng < 4; ++ng) {
                uint32_t bh[4], bl[4];
                uint32_t rb = (brow + ng * 16) * ROW_B + ks * 32 + bkof;
                LDSM_X4(bh[0], bh[1], bh[2], bh[3], sB_hi + rb);
                LDSM_X4(bl[0], bl[1], bl[2], bl[3], sB_lo + rb);
                #pragma unroll
                for (int mf = 0; mf < 4; ++mf) {
                    MMA16816(acc[mf][2*ng],   ah[mf][0], ah[mf][1], ah[mf][2], ah[mf][3],
                             bh[0], bh[1]);
                    MMA16816(acc[mf][2*ng],   ah[mf][0], ah[mf][1], ah[mf][2], ah[mf][3],
                             bl[0], bl[1]);
                    MMA16816(acc[mf][2*ng],   al[mf][0], al[mf][1], al[mf][2], al[mf][3],
                             bh[0], bh[1]);
                    MMA16816(acc[mf][2*ng+1], ah[mf][0], ah[mf][1], ah[mf][2], ah[mf][3],
                             bh[2], bh[3]);
                    MMA16816(acc[mf][2*ng+1], ah[mf][0], ah[mf][1], ah[mf][2], ah[mf][3],
                             bl[2], bl[3]);
                    MMA16816(acc[mf][2*ng+1], al[mf][0], al[mf][1], al[mf][2], al[mf][3],
                             bh[2], bh[3]);
                }
            }
        }
        __syncthreads();
        if (c + 2 < NCHUNK) { issue_stage(c + 2, st); CP_COMMIT(); }
    }

    const int mrow = lane >> 2;
    const int ncol = (lane & 3) * 2;
    #pragma unroll
    for (int mf = 0; mf < 4; ++mf) {
        #pragma unroll
        for (int nf = 0; nf < 8; ++nf) {
            int m = m0 + wm * 64 + mf * 16 + mrow;
            int n = n0 + wn * 64 + nf * 8 + ncol;
            float b0 = bias[n], b1 = bias[n + 1];
            float v00 = (acc[mf][nf][0] + b0) * scale;
            float v01 = (acc[mf][nf][1] + b1) * scale;
            float v10 = (acc[mf][nf][2] + b0) * scale;
            float v11 = (acc[mf][nf][3] + b1) * scale;
            if (MODE == 0) {
                *(float2*)&C[(size_t)m * DD + n]       = make_float2(v00, v01);
                *(float2*)&C[(size_t)(m + 8) * DD + n] = make_float2(v10, v11);
            } else {
                int b = m >> 11, h = n >> 6, d = n & 63;
                int s  = m & (SS - 1);
                size_t o0 = (((size_t)(b * HH + h)) * SS + s) * DH + d;
                size_t o1 = o0 + 8 * DH;
                __nv_bfloat16 h00 = __float2bfloat16(v00), h01 = __float2bfloat16(v01);
                __nv_bfloat16 h10 = __float2bfloat16(v10), h11 = __float2bfloat16(v11);
                *(uint32_t*)(Hi + o0) = pack_bf2(h00, h01);
                *(uint32_t*)(Hi + o1) = pack_bf2(h10, h11);
                *(uint32_t*)(Lo + o0) = pack_bf2(
                    __float2bfloat16(v00 - __bfloat162float(h00)),
                    __float2bfloat16(v01 - __bfloat162float(h01)));
                *(uint32_t*)(Lo + o1) = pack_bf2(
                    __float2bfloat16(v10 - __bfloat162float(h10)),
                    __float2bfloat16(v11 - __bfloat162float(h11)));
            }
        }
    }
}

__global__ void __launch_bounds__(GT)
qkv_mma_kernel(const float* __restrict__ bq, const float* __restrict__ bk,
               const float* __restrict__ bv) {
    int z = blockIdx.z;
    __nv_bfloat16* Hi = (z == 0) ? g_qh : (z == 1) ? g_kh : g_vh;
    __nv_bfloat16* Lo = (z == 0) ? g_ql : (z == 1) ? g_kl : g_vl;
    const float* bias = (z == 0) ? bq : (z == 1) ? bk : bv;
    float scale = (z == 0) ? QSCALE : 1.0f;
    mma_gemm_body<1>(g_x_hi, g_x_lo,
                     g_wt_hi + (size_t)z * DD * DD, g_wt_lo + (size_t)z * DD * DD,
                     bias, nullptr, Hi, Lo, scale);
}

__global__ void __launch_bounds__(GT)
outproj_mma_kernel(const float* __restrict__ bo, float* __restrict__ out) {
    mma_gemm_body<0>(g_at_hi, g_at_lo,
                     g_wt_hi + (size_t)3 * DD * DD, g_wt_lo + (size_t)3 * DD * DD,
                     bo, out, nullptr, nullptr, 1.0f);
}

// ---------------------------------------------------------------------------
// Tensor-core flash attention (split-bf16, causal, exp2 domain).
// CTA: 128 Q x 64 KV, 4 warps x 32 Q rows, 128 threads.
// P fragments stored in-place over the S accumulators (C-frag == A-frag layout).
// ---------------------------------------------------------------------------
#define AROWB 144
#define ATILE_BY (64 * AROWB)
#define AQ_BY (128 * AROWB)
#define ASTAGE_BY (4 * ATILE_BY)
#define SMEM_ATT (2 * AQ_BY + 2 * ASTAGE_BY)   // 110592
#define AT 128                                  // attention threads

__global__ void __launch_bounds__(AT, 2)
attn_mma_kernel()
{
    extern __shared__ char dynsmem[];
    const uint32_t base_u = smem_u32(dynsmem);
    const uint32_t sQh = base_u;
    const uint32_t sQl = base_u + AQ_BY;
    const uint32_t kvb = base_u + 2 * AQ_BY;

    const int tid  = threadIdx.x;
    const int w    = tid >> 5, lane = tid & 31;
    const int bh   = blockIdx.y;
    const int qt   = (int)(gridDim.x - 1 - blockIdx.x);   // heavy tiles first
    const int q0   = qt * 128;
    const int nt   = 2 * qt + 2;

    const size_t hb = (size_t)bh * SS * DH;
    const __nv_bfloat16* qhp = g_qh + hb;
    const __nv_bfloat16* qlp = g_ql + hb;
    const __nv_bfloat16* khp = g_kh + hb;
    const __nv_bfloat16* klp = g_kl + hb;
    const __nv_bfloat16* vhp = g_vh + hb;
    const __nv_bfloat16* vlp = g_vl + hb;

    auto load_q = [&]() {
        #pragma unroll
        for (int it = 0; it < 8; ++it) {
            int idx = tid + it * AT;          // 0..1023
            int row = idx >> 3, seg = idx & 7;
            CP_ASYNC16(sQh + row * AROWB + seg * 16, qhp + (size_t)(q0 + row) * DH + seg * 8);
            CP_ASYNC16(sQl + row * AROWB + seg * 16, qlp + (size_t)(q0 + row) * DH + seg * 8);
        }
    };
    auto issue_kv = [&](int kt, int st) {
        const int t0 = kt * 64;
        const __nv_bfloat16* srcs[4] = { khp, klp, vhp, vlp };
        uint32_t sb = kvb + st * ASTAGE_BY;
        #pragma unroll
        for (int tile = 0; tile < 4; ++tile) {
            const __nv_bfloat16* src = srcs[tile] + (size_t)t0 * DH;
            uint32_t dst = sb + tile * ATILE_BY;
            #pragma unroll
            for (int it = 0; it < 4; ++it) {
                int idx = tid + it * AT;      // 0..511
                int row = idx >> 3, seg = idx & 7;
                CP_ASYNC16(dst + row * AROWB + seg * 16, src + (size_t)row * DH + seg * 8);
            }
        }
    };

    load_q(); issue_kv(0, 0); CP_COMMIT();
    if (nt > 1) { issue_kv(1, 1); }
    CP_COMMIT();

    float Oa[2][8][4];
    #pragma unroll
    for (int mf = 0; mf < 2; ++mf)
        #pragma unroll
        for (int i = 0; i < 8; ++i)
            #pragma unroll
            for (int j = 0; j < 4; ++j) Oa[mf][i][j] = 0.f;
    float m_run[2][2] = {{-1e30f, -1e30f}, {-1e30f, -1e30f}};
    float l_run[2][2] = {{0.f, 0.f}, {0.f, 0.f}};

    // ldmatrix address components (warp owns rows 32w..32w+31; mf selects 16-row half)
    const uint32_t qoffA = (uint32_t)(32 * w + (lane & 15)) * AROWB + ((lane >> 4) & 1) * 16;
    const int krow = (lane & 7) + ((lane >> 4) & 1) * 8;
    const int kkof = ((lane >> 3) & 1) * 16;
    const int vrow = ((lane >> 3) & 1) * 8 + (lane & 7);
    const int vcof = ((lane >> 4) & 1) * 8;

    for (int kt = 0; kt < nt; ++kt) {
        const int st = kt & 1;
        const int t0 = kt * 64;
        if (kt + 1 < nt) CP_WAIT1(); else CP_WAIT0();
        __syncthreads();

        const uint32_t sK = kvb + st * ASTAGE_BY;
        const uint32_t sV = sK + 2 * ATILE_BY;

        // ---- S = Qh*Kh + Qh*Kl + Ql*Kh ----
        float acc[2][8][4];
        #pragma unroll
        for (int mf = 0; mf < 2; ++mf)
            #pragma unroll
            for (int i = 0; i < 8; ++i)
                #pragma unroll
                for (int j = 0; j < 4; ++j) acc[mf][i][j] = 0.f;

        #pragma unroll
        for (int ks = 0; ks < 4; ++ks) {
            uint32_t aH[2][4], aL[2][4];
            #pragma unroll
            for (int mf = 0; mf < 2; ++mf) {
                uint32_t qa = qoffA + (uint32_t)mf * 16 * AROWB + ks * 32;
                LDSM_X4(aH[mf][0], aH[mf][1], aH[mf][2], aH[mf][3], sQh + qa);
                LDSM_X4(aL[mf][0], aL[mf][1], aL[mf][2], aL[mf][3], sQl + qa);
            }
            #pragma unroll
            for (int ng = 0; ng < 4; ++ng) {
                uint32_t kb = sK + (uint32_t)(16 * ng + krow) * AROWB + ks * 32 + kkof;
                uint32_t kH[4], kL[4];
                LDSM_X4(kH[0], kH[1], kH[2], kH[3], kb);
                LDSM_X4(kL[0], kL[1], kL[2], kL[3], kb + ATILE_BY);
                #pragma unroll
                for (int mf = 0; mf < 2; ++mf) {
                    MMA16816(acc[mf][2*ng],   aH[mf][0], aH[mf][1], aH[mf][2], aH[mf][3],
                             kH[0], kH[1]);
                    MMA16816(acc[mf][2*ng],   aH[mf][0], aH[mf][1], aH[mf][2], aH[mf][3],
                             kL[0], kL[1]);
                    MMA16816(acc[mf][2*ng],   aL[mf][0], aL[mf][1], aL[mf][2], aL[mf][3],
                             kH[0], kH[1]);
                    MMA16816(acc[mf][2*ng+1], aH[mf][0], aH[mf][1], aH[mf][2], aH[mf][3],
                             kH[2], kH[3]);
                    MMA16816(acc[mf][2*ng+1], aH[mf][0], aH[mf][1], aH[mf][2], aH[mf][3],
                             kL[2], kL[3]);
                    MMA16816(acc[mf][2*ng+1], aL[mf][0], aL[mf][1], aL[mf][2], aL[mf][3],
                             kH[2], kH[3]);
                }
            }
        }

        // ---- causal mask (diagonal region only) ----
        if (kt >= 2 * qt) {
            int cb = t0 + 2 * (lane & 3);
            #pragma unroll
            for (int mf = 0; mf < 2; ++mf) {
                int rb = q0 + 32 * w + 16 * mf + (lane >> 2);
                #pragma unroll
                for (int nf = 0; nf < 8; ++nf) {
                    int c0 = cb + 8 * nf;
                    if (c0     > rb)     acc[mf][nf][0] = -1e30f;
                    if (c0 + 1 > rb)     acc[mf][nf][1] = -1e30f;
                    if (c0     > rb + 8) acc[mf][nf][2] = -1e30f;
                    if (c0 + 1 > rb + 8) acc[mf][nf][3] = -1e30f;
                }
            }
        }

        // ---- online softmax (exp2 domain); P packed in-place into acc ----
        #pragma unroll
        for (int mf = 0; mf < 2; ++mf) {
            float mx0 = -1e30f, mx1 = -1e30f;
            #pragma unroll
            for (int nf = 0; nf < 8; ++nf) {
                mx0 = fmaxf(mx0, fmaxf(acc[mf][nf][0], acc[mf][nf][1]));
                mx1 = fmaxf(mx1, fmaxf(acc[mf][nf][2], acc[mf][nf][3]));
            }
            mx0 = fmaxf(mx0, __shfl_xor_sync(0xffffffffu, mx0, 1));
            mx0 = fmaxf(mx0, __shfl_xor_sync(0xffffffffu, mx0, 2));
            mx1 = fmaxf(mx1, __shfl_xor_sync(0xffffffffu, mx1, 1));
            mx1 = fmaxf(mx1, __shfl_xor_sync(0xffffffffu, mx1, 2));

            float mn0 = fmaxf(m_run[mf][0], mx0), mn1 = fmaxf(m_run[mf][1], mx1);
            float corr0 = exp2f(m_run[mf][0] - mn0), corr1 = exp2f(m_run[mf][1] - mn1);

            float s0 = 0.f, s1 = 0.f;
            #pragma unroll
            for (int nf = 0; nf < 8; ++nf) {
                float p00 = exp2f(acc[mf][nf][0] - mn0);
                float p01 = exp2f(acc[mf][nf][1] - mn0);
                float p10 = exp2f(acc[mf][nf][2] - mn1);
                float p11 = exp2f(acc[mf][nf][3] - mn1);
                s0 += p00 + p01; s1 += p10 + p11;
                __nv_bfloat16 h00 = __float2bfloat16(p00), h01 = __float2bfloat16(p01);
                __nv_bfloat16 h10 = __float2bfloat16(p10), h11 = __float2bfloat16(p11);
                // in-place: [0]=hi(r,r+1 cols), [1]=hi(r+8), [2]=lo, [3]=lo(r+8)
                acc[mf][nf][0] = __uint_as_float(pack_bf2(h00, h01));
                acc[mf][nf][1] = __uint_as_float(pack_bf2(h10, h11));
                acc[mf][nf][2] = __uint_as_float(pack_bf2(
                    __float2bfloat16(p00 - __bfloat162float(h00)),
                    __float2bfloat16(p01 - __bfloat162float(h01))));
                acc[mf][nf][3] = __uint_as_float(pack_bf2(
                    __float2bfloat16(p10 - __bfloat162float(h10)),
                    __float2bfloat16(p11 - __bfloat162float(h11))));
            }
            s0 += __shfl_xor_sync(0xffffffffu, s0, 1);
            s0 += __shfl_xor_sync(0xffffffffu, s0, 2);
            s1 += __shfl_xor_sync(0xffffffffu, s1, 1);
            s1 += __shfl_xor_sync(0xffffffffu, s1, 2);
            l_run[mf][0] = l_run[mf][0] * corr0 + s0;  m_run[mf][0] = mn0;
            l_run[mf][1] = l_run[mf][1] * corr1 + s1;  m_run[mf][1] = mn1;

            #pragma unroll
            for (int nf = 0; nf < 8; ++nf) {
                Oa[mf][nf][0] *= corr0; Oa[mf][nf][1] *= corr0;
                Oa[mf][nf][2] *= corr1; Oa[mf][nf][3] *= corr1;
            }
        }

        // ---- O += Ph*Vh + Ph*Vl + Pl*Vh ----
        #pragma unroll
        for (int kc = 0; kc < 4; ++kc) {
            #pragma unroll
            for (int p = 0; p < 4; ++p) {
                uint32_t va = sV + (uint32_t)(16 * kc + vrow) * AROWB + (16 * p + vcof) * 2;
                uint32_t vH[4], vL[4];
                LDSM_X4_T(vH[0], vH[1], vH[2], vH[3], va);
                LDSM_X4_T(vL[0], vL[1], vL[2], vL[3], va + ATILE_BY);
                #pragma unroll
                for (int mf = 0; mf < 2; ++mf) {
                    uint32_t aH0 = __float_as_uint(acc[mf][2*kc][0]);
                    uint32_t aH1 = __float_as_uint(acc[mf][2*kc][1]);
                    uint32_t aH2 = __float_as_uint(acc[mf][2*kc+1][0]);
                    uint32_t aH3 = __float_as_uint(acc[mf][2*kc+1][1]);
                    uint32_t aL0 = __float_as_uint(acc[mf][2*kc][2]);
                    uint32_t aL1 = __float_as_uint(acc[mf][2*kc][3]);
                    uint32_t aL2 = __float_as_uint(acc[mf][2*kc+1][2]);
                    uint32_t aL3 = __float_as_uint(acc[mf][2*kc+1][3]);
                    MMA16816(Oa[mf][2*p],   aH0, aH1, aH2, aH3, vH[0], vH[1]);
                    MMA16816(Oa[mf][2*p],   aH0, aH1, aH2, aH3, vL[0], vL[1]);
                    MMA16816(Oa[mf][2*p],   aL0, aL1, aL2, aL3, vH[0], vH[1]);
                    MMA16816(Oa[mf][2*p+1], aH0, aH1, aH2, aH3, vH[2], vH[3]);
                    MMA16816(Oa[mf][2*p+1], aH0, aH1, aH2, aH3, vL[2], vL[3]);
                    MMA16816(Oa[mf][2*p+1], aL0, aL1, aL2, aL3, vH[2], vH[3]);
                }
            }
        }

        __syncthreads();
        if (kt + 2 < nt) { issue_kv(kt + 2, st); CP_COMMIT(); }
    }

    // ---- epilogue: write bf16 hi/lo into [M][D] for out projection ----
    int b = bh >> 4, h = bh & (HH - 1);
    #pragma unroll
    for (int mf = 0; mf < 2; ++mf) {
        float inv0 = 1.f / l_run[mf][0], inv1 = 1.f / l_run[mf][1];
        int r0 = q0 + 32 * w + 16 * mf + (lane >> 2);
        size_t ro0 = (size_t)(b * SS + r0) * DD + h * DH;
        size_t ro1 = ro0 + (size_t)8 * DD;
        #pragma unroll
        for (int nf = 0; nf < 8; ++nf) {
            int d = 8 * nf + 2 * (lane & 3);
            float v00 = Oa[mf][nf][0] * inv0, v01 = Oa[mf][nf][1] * inv0;
            float v10 = Oa[mf][nf][2] * inv1, v11 = Oa[mf][nf][3] * inv1;
            __nv_bfloat16 h00 = __float2bfloat16(v00), h01 = __float2bfloat16(v01);
            __nv_bfloat16 h10 = __float2bfloat16(v10), h11 = __float2bfloat16(v11);
            *(uint32_t*)(g_at_hi + ro0 + d) = pack_bf2(h00, h01);
            *(uint32_t*)(g_at_hi + ro1 + d) = pack_bf2(h10, h11);
            *(uint32_t*)(g_at_lo + ro0 + d) = pack_bf2(
                __float2bfloat16(v00 - __bfloat162float(h00)),
                __float2bfloat16(v01 - __bfloat162float(h01)));
            *(uint32_t*)(g_at_lo + ro1 + d) = pack_bf2(
                __float2bfloat16(v10 - __bfloat162float(h10)),
                __float2bfloat16(v11 - __bfloat162float(h11)));
        }
    }
}

// ---------------------------------------------------------------------------
extern "C" void kernel_launch(void* const* d_in, const int* in_sizes, int n_in,
                              void* d_out, int out_size)
{
    const float* x  = (const float*)d_in[0];
    const float* Wq = (const float*)d_in[1];
    const float* bq = (const float*)d_in[2];
    const float* Wk = (const float*)d_in[3];
    const float* bk = (const float*)d_in[4];
    const float* Wv = (const float*)d_in[5];
    const float* bv = (const float*)d_in[6];
    const float* Wo = (const float*)d_in[7];
    const float* bo = (const float*)d_in[8];
    float* out = (float*)d_out;

    cudaFuncSetAttribute(qkv_mma_kernel,
                         cudaFuncAttributeMaxDynamicSharedMemorySize, SMEM_MMA);
    cudaFuncSetAttribute(outproj_mma_kernel,
                         cudaFuncAttributeMaxDynamicSharedMemorySize, SMEM_MMA);
    cudaFuncSetAttribute(attn_mma_kernel,
                         cudaFuncAttributeMaxDynamicSharedMemorySize, SMEM_ATT);

    // 1) split x, transpose+split weights
    {
        __nv_bfloat16 *xh, *xl;
        cudaGetSymbolAddress((void**)&xh, g_x_hi);
        cudaGetSymbolAddress((void**)&xl, g_x_lo);
        split_kernel<<<(MROWS * DD) / (256 * 4), 256>>>(x, xh, xl);
        transpose_split_w<<<dim3(32, 32, 4), dim3(32, 8)>>>(Wq, Wk, Wv, Wo);
    }

    // 2) QKV projections (HMMA split-bf16, 64x64 warp tiles)
    qkv_mma_kernel<<<dim3(DD / 128, MROWS / 128, 3), GT, SMEM_MMA>>>(bq, bk, bv);

    // 3) tensor-core causal flash attention (4 warps x 32 Q rows)
    attn_mma_kernel<<<dim3(SS / 128, BB * HH), AT, SMEM_ATT>>>();

    // 4) output projection
    outproj_mma_kernel<<<dim3(DD / 128, MROWS / 128), GT, SMEM_MMA>>>(bo, out);
}